// round 13
// baseline (speedup 1.0000x reference)
#include <cuda_runtime.h>
#include <cuda_bf16.h>
#include <cstdint>

// Problem sizes (fixed by the reference).
#define B_SZ   4096
#define H_SZ   1024
#define K1_SZ  2048           // IN + H concatenated K for the gates GEMM

// GEMM tiling: CTA 128x256, warp 64x64 (8 warps), TK=64, 4-stage pipeline.
#define TM 128
#define TN 256
#define TK 64                 // K elems per stage (4 x k16)
#define ROWB 128              // bytes per smem row (TK*2, XOR swizzle, no pad)
#define NSTG 4
#define SMEM_BYTES (NSTG * (TM + TN) * ROWB)   // 196608 (192 KB)

// ---------------------------------------------------------------------------
// Scratch: device globals (no allocation allowed anywhere).
// ---------------------------------------------------------------------------
__device__ __nv_bfloat16 gA_hi[B_SZ * K1_SZ];        // [X | Hprev] hi
__device__ __nv_bfloat16 gA_lo[B_SZ * K1_SZ];        // [X | Hprev] lo
__device__ __nv_bfloat16 gW_hi[4 * H_SZ * K1_SZ];    // gate-interleaved [Wx|Wh], row = 4h+g
__device__ __nv_bfloat16 gW_lo[4 * H_SZ * K1_SZ];
__device__ __nv_bfloat16 gWo_hi[H_SZ * H_SZ];        // W_out
__device__ __nv_bfloat16 gWo_lo[H_SZ * H_SZ];
__device__ __nv_bfloat16 gHid_hi[B_SZ * H_SZ];       // new_hidden (bf16 split, for GEMM2)
__device__ __nv_bfloat16 gHid_lo[B_SZ * H_SZ];

__device__ __forceinline__ void split_bf16(float v, __nv_bfloat16* hi, __nv_bfloat16* lo) {
    __nv_bfloat16 h = __float2bfloat16(v);
    *hi = h;
    *lo = __float2bfloat16(v - __bfloat162float(h));
}

// ---------------------------------------------------------------------------
// Conversion kernels
// ---------------------------------------------------------------------------
__global__ void convertA_kernel(const float* __restrict__ X, const float* __restrict__ Hv) {
    int idx = blockIdx.x * blockDim.x + threadIdx.x;   // over B_SZ * K1_SZ
    int k = idx & (K1_SZ - 1);
    int m = idx >> 11;
    float v = (k < 1024) ? X[(m << 10) + k] : Hv[(m << 10) + (k - 1024)];
    split_bf16(v, &gA_hi[idx], &gA_lo[idx]);
}

// Packed weight row r = 4*h + gate; cols k<1024 from Wx_gate[h], k>=1024 from Wh_gate[h].
__global__ void convertW_kernel(const float* __restrict__ Wxf, const float* __restrict__ Wxi,
                                const float* __restrict__ Wxo, const float* __restrict__ Wxg,
                                const float* __restrict__ Whf, const float* __restrict__ Whi,
                                const float* __restrict__ Who, const float* __restrict__ Whg) {
    int idx = blockIdx.x * blockDim.x + threadIdx.x;   // over 4*H_SZ * K1_SZ
    int k = idx & (K1_SZ - 1);
    int rrow = idx >> 11;
    int h = rrow >> 2, g = rrow & 3;
    const float* p;
    if (k < 1024) {
        p = (g == 0) ? Wxf : (g == 1) ? Wxi : (g == 2) ? Wxo : Wxg;
        p += (h << 10) + k;
    } else {
        p = (g == 0) ? Whf : (g == 1) ? Whi : (g == 2) ? Who : Whg;
        p += (h << 10) + (k - 1024);
    }
    split_bf16(*p, &gW_hi[idx], &gW_lo[idx]);
}

__global__ void convertWo_kernel(const float* __restrict__ Wo) {
    int idx = blockIdx.x * blockDim.x + threadIdx.x;   // over H_SZ*H_SZ
    split_bf16(Wo[idx], &gWo_hi[idx], &gWo_lo[idx]);
}

// ---------------------------------------------------------------------------
// cp.async / ldmatrix helpers
// ---------------------------------------------------------------------------
__device__ __forceinline__ void cp16s(uint32_t sa, const void* g) {
    asm volatile("cp.async.cg.shared.global [%0], [%1], 16;\n" :: "r"(sa), "l"(g));
}

__device__ __forceinline__ void ldsm_x4(uint32_t& r0, uint32_t& r1, uint32_t& r2, uint32_t& r3,
                                        uint32_t addr) {
    asm volatile("ldmatrix.sync.aligned.m8n8.x4.shared.b16 {%0,%1,%2,%3}, [%4];"
                 : "=r"(r0), "=r"(r1), "=r"(r2), "=r"(r3) : "r"(addr));
}

// ---------------------------------------------------------------------------
// Split-bf16 GEMM: C = A_hi*W_hi + A_hi*W_lo + A_lo*W_hi   (three K passes)
// CTA 128x256, warp 64x64. XOR-swizzled 128B smem rows:
//   smem_off(row, cb) = row*128 + (cb ^ ((row&7)*16))
// 4-stage circular cp.async pipeline, one __syncthreads per stage:
//   iter kt: wait_group 2 (stage kt resident); barrier; load kt+3 into
//   buffer (kt+3)%4 == (kt-1)%4 (readers done before this barrier).
// MODE 0: gates GEMM + fused LSTM-cell epilogue. MODE 1: output GEMM + bias.
// ---------------------------------------------------------------------------
template<int KP, int MODE>
__global__ __launch_bounds__(256, 1)
void gemm_kernel(const float* __restrict__ cellv,
                 const float* __restrict__ bF, const float* __restrict__ bI,
                 const float* __restrict__ bO, const float* __restrict__ bG,
                 float* __restrict__ out0, float* __restrict__ out1,
                 const float* __restrict__ bOut) {
    constexpr int NKT = KP / TK;
    constexpr int TOT = 3 * NKT;

    const __nv_bfloat16* __restrict__ Ahi = (MODE == 0) ? gA_hi : gHid_hi;
    const __nv_bfloat16* __restrict__ Alo = (MODE == 0) ? gA_lo : gHid_lo;
    const __nv_bfloat16* __restrict__ Whi = (MODE == 0) ? gW_hi : gWo_hi;
    const __nv_bfloat16* __restrict__ Wlo = (MODE == 0) ? gW_lo : gWo_lo;

    extern __shared__ __nv_bfloat16 smem[];
    const uint32_t smem_u32 = (uint32_t)__cvta_generic_to_shared(smem);
    const uint32_t sA0 = smem_u32;                       // NSTG bufs of TM*128 B
    const uint32_t sB0 = smem_u32 + NSTG * TM * ROWB;    // NSTG bufs of TN*128 B

    const int tid = threadIdx.x;
    const int lane = tid & 31, warp = tid >> 5;
    const int wm = warp >> 2, wn = warp & 3;     // warp grid 2(M) x 4(N), 64x64 each
    const int r = lane >> 2, q = lane & 3;
    const int bm = blockIdx.y, bn = blockIdx.x;

    float acc[4][8][4];
    #pragma unroll
    for (int i = 0; i < 4; i++)
        #pragma unroll
        for (int j = 0; j < 8; j++)
            #pragma unroll
            for (int k = 0; k < 4; k++) acc[i][j][k] = 0.f;

    // cp.async indexing: 8 chunks of 16B per 128B row.
    const int ld_row = tid >> 3;          // 0..31 (+32*t)
    const int ld_cb  = (tid & 7) * 16;    // byte col within row

    // ldmatrix per-thread source rows (within tile) and column bytes.
    const int a_row  = wm * 64 + (lane & 15);                         // + mf*16
    const int a_cb0  = (lane >> 4) * 16;                              // k-half (bytes)
    const int a_xor  = (a_row & 7) * 16;
    const int b_row  = wn * 64 + (lane & 7) + ((lane >> 4) & 1) * 8;  // + nfp*16
    const int b_cb0  = ((lane >> 3) & 1) * 16;
    const int b_xor  = (b_row & 7) * 16;

    auto load_stage = [&](int kt, int buf) {
        int seg = (kt >= 2 * NKT) ? 2 : ((kt >= NKT) ? 1 : 0);
        int kk = (kt - seg * NKT) * TK;
        const __nv_bfloat16* Ap = ((seg == 2) ? Alo : Ahi) + (size_t)(bm * TM) * KP + kk;
        const __nv_bfloat16* Wp = ((seg == 1) ? Wlo : Whi) + (size_t)(bn * TN) * KP + kk;
        const uint32_t dA = sA0 + buf * (TM * ROWB);
        const uint32_t dB = sB0 + buf * (TN * ROWB);
        const uint32_t swcb = ld_cb ^ ((ld_row & 7) * 16);   // row&7 invariant under +32
        #pragma unroll
        for (int t = 0; t < 4; t++) {                        // A: 128 rows
            int row = ld_row + t * 32;
            cp16s(dA + row * ROWB + swcb, Ap + (size_t)row * KP + ld_cb / 2);
        }
        #pragma unroll
        for (int t = 0; t < 8; t++) {                        // B: 256 rows
            int row = ld_row + t * 32;
            cp16s(dB + row * ROWB + swcb, Wp + (size_t)row * KP + ld_cb / 2);
        }
        asm volatile("cp.async.commit_group;\n");
    };

    // Prologue: stages 0,1,2 in flight.
    load_stage(0, 0);
    load_stage(1, 1);
    load_stage(2, 2);

    for (int kt = 0; kt < TOT; kt++) {
        const int buf = kt % NSTG;
        asm volatile("cp.async.wait_group 2;\n");   // stage kt resident
        __syncthreads();                            // visibility + WAR fence

        if (kt + 3 < TOT) {
            load_stage(kt + 3, (kt + 3) % NSTG);
        } else {
            asm volatile("cp.async.commit_group;\n");   // keep group counts aligned
        }

        const uint32_t aBuf = sA0 + (uint32_t)(buf * (TM * ROWB));
        const uint32_t bBuf = sB0 + (uint32_t)(buf * (TN * ROWB));

        #pragma unroll
        for (int ks = 0; ks < TK; ks += 16) {
            uint32_t af[4][4], bfr[8][2];
            const uint32_t acol = (uint32_t)((a_cb0 + ks * 2) ^ a_xor);
            const uint32_t bcol = (uint32_t)((b_cb0 + ks * 2) ^ b_xor);
            #pragma unroll
            for (int mf = 0; mf < 4; mf++) {
                uint32_t addr = aBuf + (uint32_t)((a_row + mf * 16) * ROWB) + acol;
                ldsm_x4(af[mf][0], af[mf][1], af[mf][2], af[mf][3], addr);
            }
            #pragma unroll
            for (int nfp = 0; nfp < 4; nfp++) {
                uint32_t addr = bBuf + (uint32_t)((b_row + nfp * 16) * ROWB) + bcol;
                ldsm_x4(bfr[2 * nfp][0], bfr[2 * nfp][1],
                        bfr[2 * nfp + 1][0], bfr[2 * nfp + 1][1], addr);
            }
            #pragma unroll
            for (int mf = 0; mf < 4; mf++)
                #pragma unroll
                for (int nf = 0; nf < 8; nf++) {
                    asm volatile(
                        "mma.sync.aligned.m16n8k16.row.col.f32.bf16.bf16.f32 "
                        "{%0,%1,%2,%3}, {%4,%5,%6,%7}, {%8,%9}, {%0,%1,%2,%3};\n"
                        : "+f"(acc[mf][nf][0]), "+f"(acc[mf][nf][1]),
                          "+f"(acc[mf][nf][2]), "+f"(acc[mf][nf][3])
                        : "r"(af[mf][0]), "r"(af[mf][1]), "r"(af[mf][2]), "r"(af[mf][3]),
                          "r"(bfr[nf][0]), "r"(bfr[nf][1]));
                }
        }
        // No trailing barrier: next iteration's barrier provides the WAR fence.
    }

    if constexpr (MODE == 0) {
        // Packed column 4h+g. Even lane holds (f,i) pre-acts, odd lane (o,g) of same h.
        const bool writer = ((lane & 1) == 0);
        #pragma unroll
        for (int mf = 0; mf < 4; mf++) {
            #pragma unroll
            for (int nf = 0; nf < 8; nf++) {
                float v0 = acc[mf][nf][0], v1 = acc[mf][nf][1];
                float v2 = acc[mf][nf][2], v3 = acc[mf][nf][3];
                float p0 = __shfl_xor_sync(0xffffffffu, v0, 1);
                float p1 = __shfl_xor_sync(0xffffffffu, v1, 1);
                float p2 = __shfl_xor_sync(0xffffffffu, v2, 1);
                float p3 = __shfl_xor_sync(0xffffffffu, v3, 1);
                if (writer) {
                    int ncol = bn * TN + wn * 64 + nf * 8 + q * 2;   // multiple of 4
                    int h = ncol >> 2;
                    float bf_ = bF[h], bi_ = bI[h], bo_ = bO[h], bg_ = bG[h];
                    int row = bm * TM + wm * 64 + mf * 16 + r;
                    #pragma unroll
                    for (int half = 0; half < 2; half++) {
                        float pf, pi, po, pg;
                        if (half == 0) { pf = v0 + bf_; pi = v1 + bi_; po = p0 + bo_; pg = p1 + bg_; }
                        else           { pf = v2 + bf_; pi = v3 + bi_; po = p2 + bo_; pg = p3 + bg_; }
                        int rr = row + half * 8;
                        float fg = 1.f / (1.f + __expf(-pf));
                        float ig = 1.f / (1.f + __expf(-pi));
                        float og = 1.f / (1.f + __expf(-po));
                        float gg = tanhf(pg);
                        float cold = cellv[rr * H_SZ + h];
                        float ncell = fg * cold + ig * gg;
                        float nhid = og * tanhf(ncell);
                        out0[rr * H_SZ + h] = nhid;    // new_hidden
                        out1[rr * H_SZ + h] = ncell;   // new_cell
                        split_bf16(nhid, &gHid_hi[rr * H_SZ + h], &gHid_lo[rr * H_SZ + h]);
                    }
                }
            }
        }
    } else {
        #pragma unroll
        for (int mf = 0; mf < 4; mf++) {
            int row = bm * TM + wm * 64 + mf * 16 + r;
            #pragma unroll
            for (int nf = 0; nf < 8; nf++) {
                int c0 = bn * TN + wn * 64 + nf * 8 + q * 2;
                float b0 = bOut[c0], b1 = bOut[c0 + 1];
                out0[row * H_SZ + c0]           = acc[mf][nf][0] + b0;
                out0[row * H_SZ + c0 + 1]       = acc[mf][nf][1] + b1;
                out0[(row + 8) * H_SZ + c0]     = acc[mf][nf][2] + b0;
                out0[(row + 8) * H_SZ + c0 + 1] = acc[mf][nf][3] + b1;
            }
        }
    }
}

// ---------------------------------------------------------------------------
// Launch
// ---------------------------------------------------------------------------
extern "C" void kernel_launch(void* const* d_in, const int* in_sizes, int n_in,
                              void* d_out, int out_size) {
    const float* X   = (const float*)d_in[0];
    const float* Hv  = (const float*)d_in[1];
    const float* Cv  = (const float*)d_in[2];
    const float* Wxf = (const float*)d_in[3];
    const float* bxf = (const float*)d_in[4];
    const float* Whf = (const float*)d_in[5];
    const float* Wxi = (const float*)d_in[6];
    const float* bxi = (const float*)d_in[7];
    const float* Whi = (const float*)d_in[8];
    const float* Wxo = (const float*)d_in[9];
    const float* bxo = (const float*)d_in[10];
    const float* Who = (const float*)d_in[11];
    const float* Wxg = (const float*)d_in[12];
    const float* bxg = (const float*)d_in[13];
    const float* Whg = (const float*)d_in[14];
    const float* Wo  = (const float*)d_in[15];
    const float* bo  = (const float*)d_in[16];

    float* nh = (float*)d_out;
    float* nc = nh + (size_t)B_SZ * H_SZ;
    float* ov = nc + (size_t)B_SZ * H_SZ;

    convertA_kernel<<<(B_SZ * K1_SZ) / 256, 256>>>(X, Hv);
    convertW_kernel<<<(4 * H_SZ * K1_SZ) / 256, 256>>>(Wxf, Wxi, Wxo, Wxg, Whf, Whi, Who, Whg);
    convertWo_kernel<<<(H_SZ * H_SZ) / 256, 256>>>(Wo);

    cudaFuncSetAttribute(gemm_kernel<K1_SZ, 0>,
                         cudaFuncAttributeMaxDynamicSharedMemorySize, SMEM_BYTES);
    cudaFuncSetAttribute(gemm_kernel<H_SZ, 1>,
                         cudaFuncAttributeMaxDynamicSharedMemorySize, SMEM_BYTES);

    dim3 g1(4 * H_SZ / TN, B_SZ / TM);   // (16, 32) = 512 CTAs
    gemm_kernel<K1_SZ, 0><<<g1, 256, SMEM_BYTES>>>(Cv, bxf, bxi, bxo, bxg, nh, nc, nullptr);

    dim3 g2(H_SZ / TN, B_SZ / TM);       // (4, 32) = 128 CTAs
    gemm_kernel<H_SZ, 1><<<g2, 256, SMEM_BYTES>>>(nullptr, nullptr, nullptr, nullptr, nullptr,
                                                  ov, nullptr, bo);
}

// round 14
// speedup vs baseline: 1.1038x; 1.1038x over previous
#include <cuda_runtime.h>
#include <cuda_bf16.h>
#include <cstdint>

// Problem sizes (fixed by the reference).
#define B_SZ   4096
#define H_SZ   1024
#define K1_SZ  2048           // IN + H concatenated K for the gates GEMM

// GEMM tiling: CTA 128x128, warp 64x64 (4 warps, 128 thr), TK=64, 3 stages.
#define TM 128
#define TN 128
#define TK 64                 // K elems per stage (4 x k16)
#define ROWB 128              // bytes per smem row (TK*2, XOR swizzle, no pad)
#define NSTG 3
#define SMEM_BYTES (NSTG * (TM + TN) * ROWB)   // 98304 (96 KB) -> 2 CTA/SM

// ---------------------------------------------------------------------------
// Scratch: device globals (no allocation allowed anywhere).
// ---------------------------------------------------------------------------
__device__ __nv_bfloat16 gA_hi[B_SZ * K1_SZ];        // [X | Hprev] hi
__device__ __nv_bfloat16 gA_lo[B_SZ * K1_SZ];        // [X | Hprev] lo
__device__ __nv_bfloat16 gW_hi[4 * H_SZ * K1_SZ];    // gate-interleaved [Wx|Wh], row = 4h+g
__device__ __nv_bfloat16 gW_lo[4 * H_SZ * K1_SZ];
__device__ __nv_bfloat16 gWo_hi[H_SZ * H_SZ];        // W_out
__device__ __nv_bfloat16 gWo_lo[H_SZ * H_SZ];
__device__ __nv_bfloat16 gHid_hi[B_SZ * H_SZ];       // new_hidden (bf16 split, for GEMM2)
__device__ __nv_bfloat16 gHid_lo[B_SZ * H_SZ];

__device__ __forceinline__ void split_bf16(float v, __nv_bfloat16* hi, __nv_bfloat16* lo) {
    __nv_bfloat16 h = __float2bfloat16(v);
    *hi = h;
    *lo = __float2bfloat16(v - __bfloat162float(h));
}

// ---------------------------------------------------------------------------
// Conversion kernels
// ---------------------------------------------------------------------------
__global__ void convertA_kernel(const float* __restrict__ X, const float* __restrict__ Hv) {
    int idx = blockIdx.x * blockDim.x + threadIdx.x;   // over B_SZ * K1_SZ
    int k = idx & (K1_SZ - 1);
    int m = idx >> 11;
    float v = (k < 1024) ? X[(m << 10) + k] : Hv[(m << 10) + (k - 1024)];
    split_bf16(v, &gA_hi[idx], &gA_lo[idx]);
}

// Packed weight row r = 4*h + gate; cols k<1024 from Wx_gate[h], k>=1024 from Wh_gate[h].
__global__ void convertW_kernel(const float* __restrict__ Wxf, const float* __restrict__ Wxi,
                                const float* __restrict__ Wxo, const float* __restrict__ Wxg,
                                const float* __restrict__ Whf, const float* __restrict__ Whi,
                                const float* __restrict__ Who, const float* __restrict__ Whg) {
    int idx = blockIdx.x * blockDim.x + threadIdx.x;   // over 4*H_SZ * K1_SZ
    int k = idx & (K1_SZ - 1);
    int rrow = idx >> 11;
    int h = rrow >> 2, g = rrow & 3;
    const float* p;
    if (k < 1024) {
        p = (g == 0) ? Wxf : (g == 1) ? Wxi : (g == 2) ? Wxo : Wxg;
        p += (h << 10) + k;
    } else {
        p = (g == 0) ? Whf : (g == 1) ? Whi : (g == 2) ? Who : Whg;
        p += (h << 10) + (k - 1024);
    }
    split_bf16(*p, &gW_hi[idx], &gW_lo[idx]);
}

__global__ void convertWo_kernel(const float* __restrict__ Wo) {
    int idx = blockIdx.x * blockDim.x + threadIdx.x;   // over H_SZ*H_SZ
    split_bf16(Wo[idx], &gWo_hi[idx], &gWo_lo[idx]);
}

// ---------------------------------------------------------------------------
// cp.async / ldmatrix helpers
// ---------------------------------------------------------------------------
__device__ __forceinline__ void cp16s(uint32_t sa, const void* g) {
    asm volatile("cp.async.cg.shared.global [%0], [%1], 16;\n" :: "r"(sa), "l"(g));
}

__device__ __forceinline__ void ldsm_x4(uint32_t& r0, uint32_t& r1, uint32_t& r2, uint32_t& r3,
                                        uint32_t addr) {
    asm volatile("ldmatrix.sync.aligned.m8n8.x4.shared.b16 {%0,%1,%2,%3}, [%4];"
                 : "=r"(r0), "=r"(r1), "=r"(r2), "=r"(r3) : "r"(addr));
}

// ---------------------------------------------------------------------------
// Split-bf16 GEMM: C = A_hi*W_hi + A_hi*W_lo + A_lo*W_hi   (three K passes)
// CTA 128x128, 4 warps of 64x64. XOR-swizzled 128B smem rows:
//   smem_off(row, cb) = row*128 + (cb ^ ((row&7)*16))
// 3-stage circular cp.async pipeline, one __syncthreads per stage (R11 scheme):
//   iter kt: wait_group 1; barrier; load kt+2 into buffer (kt+2)%3 == (kt-1)%3.
// MODE 0: gates GEMM + fused LSTM-cell epilogue. MODE 1: output GEMM + bias.
// ---------------------------------------------------------------------------
template<int KP, int MODE>
__global__ __launch_bounds__(128, 2)
void gemm_kernel(const float* __restrict__ cellv,
                 const float* __restrict__ bF, const float* __restrict__ bI,
                 const float* __restrict__ bO, const float* __restrict__ bG,
                 float* __restrict__ out0, float* __restrict__ out1,
                 const float* __restrict__ bOut) {
    constexpr int NKT = KP / TK;
    constexpr int TOT = 3 * NKT;

    const __nv_bfloat16* __restrict__ Ahi = (MODE == 0) ? gA_hi : gHid_hi;
    const __nv_bfloat16* __restrict__ Alo = (MODE == 0) ? gA_lo : gHid_lo;
    const __nv_bfloat16* __restrict__ Whi = (MODE == 0) ? gW_hi : gWo_hi;
    const __nv_bfloat16* __restrict__ Wlo = (MODE == 0) ? gW_lo : gWo_lo;

    extern __shared__ __nv_bfloat16 smem[];
    const uint32_t smem_u32 = (uint32_t)__cvta_generic_to_shared(smem);
    const uint32_t sA0 = smem_u32;                       // NSTG bufs of TM*128 B
    const uint32_t sB0 = smem_u32 + NSTG * TM * ROWB;    // NSTG bufs of TN*128 B

    const int tid = threadIdx.x;
    const int lane = tid & 31, warp = tid >> 5;
    const int wm = warp >> 1, wn = warp & 1;     // warp grid 2(M) x 2(N), 64x64 each
    const int r = lane >> 2, q = lane & 3;
    const int bm = blockIdx.y, bn = blockIdx.x;

    float acc[4][8][4];
    #pragma unroll
    for (int i = 0; i < 4; i++)
        #pragma unroll
        for (int j = 0; j < 8; j++)
            #pragma unroll
            for (int k = 0; k < 4; k++) acc[i][j][k] = 0.f;

    // cp.async indexing: 8 chunks of 16B per 128B row, 128 threads.
    const int ld_row = tid >> 3;          // 0..15 (+16*t)
    const int ld_cb  = (tid & 7) * 16;    // byte col within row

    // ldmatrix per-thread source rows (within tile) and column bytes.
    const int a_row  = wm * 64 + (lane & 15);                         // + mf*16
    const int a_cb0  = (lane >> 4) * 16;                              // k-half (bytes)
    const int a_xor  = (a_row & 7) * 16;
    const int b_row  = wn * 64 + (lane & 7) + ((lane >> 4) & 1) * 8;  // + nfp*16
    const int b_cb0  = ((lane >> 3) & 1) * 16;
    const int b_xor  = (b_row & 7) * 16;

    auto load_stage = [&](int kt, int buf) {
        int seg = (kt >= 2 * NKT) ? 2 : ((kt >= NKT) ? 1 : 0);
        int kk = (kt - seg * NKT) * TK;
        const __nv_bfloat16* Ap = ((seg == 2) ? Alo : Ahi) + (size_t)(bm * TM) * KP + kk;
        const __nv_bfloat16* Wp = ((seg == 1) ? Wlo : Whi) + (size_t)(bn * TN) * KP + kk;
        const uint32_t dA = sA0 + buf * (TM * ROWB);
        const uint32_t dB = sB0 + buf * (TN * ROWB);
        const uint32_t swcb = ld_cb ^ ((ld_row & 7) * 16);   // row&7 invariant under +16
        #pragma unroll
        for (int t = 0; t < 8; t++) {                        // A: 128 rows
            int row = ld_row + t * 16;
            cp16s(dA + row * ROWB + swcb, Ap + (size_t)row * KP + ld_cb / 2);
        }
        #pragma unroll
        for (int t = 0; t < 8; t++) {                        // B: 128 rows
            int row = ld_row + t * 16;
            cp16s(dB + row * ROWB + swcb, Wp + (size_t)row * KP + ld_cb / 2);
        }
        asm volatile("cp.async.commit_group;\n");
    };

    // Prologue: stages 0 and 1 in flight.
    load_stage(0, 0);
    load_stage(1, 1);

    for (int kt = 0; kt < TOT; kt++) {
        const int buf = kt % NSTG;
        asm volatile("cp.async.wait_group 1;\n");   // stage kt resident
        __syncthreads();                            // visibility + WAR fence

        if (kt + 2 < TOT) {
            load_stage(kt + 2, (kt + 2) % NSTG);
        } else {
            asm volatile("cp.async.commit_group;\n");   // keep group counts aligned
        }

        const uint32_t aBuf = sA0 + (uint32_t)(buf * (TM * ROWB));
        const uint32_t bBuf = sB0 + (uint32_t)(buf * (TN * ROWB));

        #pragma unroll
        for (int ks = 0; ks < TK; ks += 16) {
            uint32_t af[4][4], bfr[8][2];
            const uint32_t acol = (uint32_t)((a_cb0 + ks * 2) ^ a_xor);
            const uint32_t bcol = (uint32_t)((b_cb0 + ks * 2) ^ b_xor);
            #pragma unroll
            for (int mf = 0; mf < 4; mf++) {
                uint32_t addr = aBuf + (uint32_t)((a_row + mf * 16) * ROWB) + acol;
                ldsm_x4(af[mf][0], af[mf][1], af[mf][2], af[mf][3], addr);
            }
            #pragma unroll
            for (int nfp = 0; nfp < 4; nfp++) {
                uint32_t addr = bBuf + (uint32_t)((b_row + nfp * 16) * ROWB) + bcol;
                ldsm_x4(bfr[2 * nfp][0], bfr[2 * nfp][1],
                        bfr[2 * nfp + 1][0], bfr[2 * nfp + 1][1], addr);
            }
            #pragma unroll
            for (int mf = 0; mf < 4; mf++)
                #pragma unroll
                for (int nf = 0; nf < 8; nf++) {
                    asm volatile(
                        "mma.sync.aligned.m16n8k16.row.col.f32.bf16.bf16.f32 "
                        "{%0,%1,%2,%3}, {%4,%5,%6,%7}, {%8,%9}, {%0,%1,%2,%3};\n"
                        : "+f"(acc[mf][nf][0]), "+f"(acc[mf][nf][1]),
                          "+f"(acc[mf][nf][2]), "+f"(acc[mf][nf][3])
                        : "r"(af[mf][0]), "r"(af[mf][1]), "r"(af[mf][2]), "r"(af[mf][3]),
                          "r"(bfr[nf][0]), "r"(bfr[nf][1]));
                }
        }
        // No trailing barrier: next iteration's barrier provides the WAR fence.
    }

    if constexpr (MODE == 0) {
        // Packed column 4h+g. Even lane holds (f,i) pre-acts, odd lane (o,g) of same h.
        const bool writer = ((lane & 1) == 0);
        #pragma unroll
        for (int mf = 0; mf < 4; mf++) {
            #pragma unroll
            for (int nf = 0; nf < 8; nf++) {
                float v0 = acc[mf][nf][0], v1 = acc[mf][nf][1];
                float v2 = acc[mf][nf][2], v3 = acc[mf][nf][3];
                float p0 = __shfl_xor_sync(0xffffffffu, v0, 1);
                float p1 = __shfl_xor_sync(0xffffffffu, v1, 1);
                float p2 = __shfl_xor_sync(0xffffffffu, v2, 1);
                float p3 = __shfl_xor_sync(0xffffffffu, v3, 1);
                if (writer) {
                    int ncol = bn * TN + wn * 64 + nf * 8 + q * 2;   // multiple of 4
                    int h = ncol >> 2;
                    float bf_ = bF[h], bi_ = bI[h], bo_ = bO[h], bg_ = bG[h];
                    int row = bm * TM + wm * 64 + mf * 16 + r;
                    #pragma unroll
                    for (int half = 0; half < 2; half++) {
                        float pf, pi, po, pg;
                        if (half == 0) { pf = v0 + bf_; pi = v1 + bi_; po = p0 + bo_; pg = p1 + bg_; }
                        else           { pf = v2 + bf_; pi = v3 + bi_; po = p2 + bo_; pg = p3 + bg_; }
                        int rr = row + half * 8;
                        float fg = 1.f / (1.f + __expf(-pf));
                        float ig = 1.f / (1.f + __expf(-pi));
                        float og = 1.f / (1.f + __expf(-po));
                        float gg = tanhf(pg);
                        float cold = cellv[rr * H_SZ + h];
                        float ncell = fg * cold + ig * gg;
                        float nhid = og * tanhf(ncell);
                        out0[rr * H_SZ + h] = nhid;    // new_hidden
                        out1[rr * H_SZ + h] = ncell;   // new_cell
                        split_bf16(nhid, &gHid_hi[rr * H_SZ + h], &gHid_lo[rr * H_SZ + h]);
                    }
                }
            }
        }
    } else {
        #pragma unroll
        for (int mf = 0; mf < 4; mf++) {
            int row = bm * TM + wm * 64 + mf * 16 + r;
            #pragma unroll
            for (int nf = 0; nf < 8; nf++) {
                int c0 = bn * TN + wn * 64 + nf * 8 + q * 2;
                float b0 = bOut[c0], b1 = bOut[c0 + 1];
                out0[row * H_SZ + c0]           = acc[mf][nf][0] + b0;
                out0[row * H_SZ + c0 + 1]       = acc[mf][nf][1] + b1;
                out0[(row + 8) * H_SZ + c0]     = acc[mf][nf][2] + b0;
                out0[(row + 8) * H_SZ + c0 + 1] = acc[mf][nf][3] + b1;
            }
        }
    }
}

// ---------------------------------------------------------------------------
// Launch
// ---------------------------------------------------------------------------
extern "C" void kernel_launch(void* const* d_in, const int* in_sizes, int n_in,
                              void* d_out, int out_size) {
    const float* X   = (const float*)d_in[0];
    const float* Hv  = (const float*)d_in[1];
    const float* Cv  = (const float*)d_in[2];
    const float* Wxf = (const float*)d_in[3];
    const float* bxf = (const float*)d_in[4];
    const float* Whf = (const float*)d_in[5];
    const float* Wxi = (const float*)d_in[6];
    const float* bxi = (const float*)d_in[7];
    const float* Whi = (const float*)d_in[8];
    const float* Wxo = (const float*)d_in[9];
    const float* bxo = (const float*)d_in[10];
    const float* Who = (const float*)d_in[11];
    const float* Wxg = (const float*)d_in[12];
    const float* bxg = (const float*)d_in[13];
    const float* Whg = (const float*)d_in[14];
    const float* Wo  = (const float*)d_in[15];
    const float* bo  = (const float*)d_in[16];

    float* nh = (float*)d_out;
    float* nc = nh + (size_t)B_SZ * H_SZ;
    float* ov = nc + (size_t)B_SZ * H_SZ;

    convertA_kernel<<<(B_SZ * K1_SZ) / 256, 256>>>(X, Hv);
    convertW_kernel<<<(4 * H_SZ * K1_SZ) / 256, 256>>>(Wxf, Wxi, Wxo, Wxg, Whf, Whi, Who, Whg);
    convertWo_kernel<<<(H_SZ * H_SZ) / 256, 256>>>(Wo);

    cudaFuncSetAttribute(gemm_kernel<K1_SZ, 0>,
                         cudaFuncAttributeMaxDynamicSharedMemorySize, SMEM_BYTES);
    cudaFuncSetAttribute(gemm_kernel<H_SZ, 1>,
                         cudaFuncAttributeMaxDynamicSharedMemorySize, SMEM_BYTES);

    dim3 g1(4 * H_SZ / TN, B_SZ / TM);   // (32, 32) = 1024 CTAs
    gemm_kernel<K1_SZ, 0><<<g1, 128, SMEM_BYTES>>>(Cv, bxf, bxi, bxo, bxg, nh, nc, nullptr);

    dim3 g2(H_SZ / TN, B_SZ / TM);       // (8, 32) = 256 CTAs
    gemm_kernel<H_SZ, 1><<<g2, 128, SMEM_BYTES>>>(nullptr, nullptr, nullptr, nullptr, nullptr,
                                                  ov, nullptr, bo);
}

// round 16
// speedup vs baseline: 1.7218x; 1.5600x over previous
#include <cuda_runtime.h>
#include <cuda_fp16.h>
#include <cstdint>

// Problem sizes (fixed by the reference).
#define B_SZ   4096
#define H_SZ   1024
#define K1_SZ  2048           // IN + H concatenated K for the gates GEMM

// GEMM tiling (R11-proven config): CTA 128x128, 8 warps of 64x32, TK=64, 3 stages.
#define TM 128
#define TN 128
#define TK 64                 // K elems per stage (4 x k16)
#define ROWB 128              // bytes per smem row (TK*2, XOR swizzle, no pad)
#define NSTG 3
#define SMEM_BYTES (NSTG * (TM + TN) * ROWB)   // 98304 (96 KB) -> 2 CTA/SM

// ---------------------------------------------------------------------------
// Scratch: device globals (no allocation allowed anywhere).
// fp16 split: A = Ahi + Alo (exact to ~2^-22); W rounded once to fp16.
// GEMM = Ahi*Whi + Alo*Whi  == A * fl16(W)  (2 passes, not 3).
// ---------------------------------------------------------------------------
__device__ __half gA_hi[B_SZ * K1_SZ];        // [X | Hprev] hi
__device__ __half gA_lo[B_SZ * K1_SZ];        // [X | Hprev] residual
__device__ __half gW_hi[4 * H_SZ * K1_SZ];    // gate-interleaved [Wx|Wh], row = 4h+g
__device__ __half gWo_hi[H_SZ * H_SZ];        // W_out
__device__ __half gHid_hi[B_SZ * H_SZ];       // new_hidden hi (for GEMM2)
__device__ __half gHid_lo[B_SZ * H_SZ];       // new_hidden residual

__device__ __forceinline__ void split_f16(float v, __half* hi, __half* lo) {
    __half h = __float2half_rn(v);
    *hi = h;
    *lo = __float2half_rn(v - __half2float(h));
}

// ---------------------------------------------------------------------------
// Conversion kernels
// ---------------------------------------------------------------------------
__global__ void convertA_kernel(const float* __restrict__ X, const float* __restrict__ Hv) {
    int idx = blockIdx.x * blockDim.x + threadIdx.x;   // over B_SZ * K1_SZ
    int k = idx & (K1_SZ - 1);
    int m = idx >> 11;
    float v = (k < 1024) ? X[(m << 10) + k] : Hv[(m << 10) + (k - 1024)];
    split_f16(v, &gA_hi[idx], &gA_lo[idx]);
}

// Packed weight row r = 4*h + gate; cols k<1024 from Wx_gate[h], k>=1024 from Wh_gate[h].
__global__ void convertW_kernel(const float* __restrict__ Wxf, const float* __restrict__ Wxi,
                                const float* __restrict__ Wxo, const float* __restrict__ Wxg,
                                const float* __restrict__ Whf, const float* __restrict__ Whi,
                                const float* __restrict__ Who, const float* __restrict__ Whg) {
    int idx = blockIdx.x * blockDim.x + threadIdx.x;   // over 4*H_SZ * K1_SZ
    int k = idx & (K1_SZ - 1);
    int rrow = idx >> 11;
    int h = rrow >> 2, g = rrow & 3;
    const float* p;
    if (k < 1024) {
        p = (g == 0) ? Wxf : (g == 1) ? Wxi : (g == 2) ? Wxo : Wxg;
        p += (h << 10) + k;
    } else {
        p = (g == 0) ? Whf : (g == 1) ? Whi : (g == 2) ? Who : Whg;
        p += (h << 10) + (k - 1024);
    }
    gW_hi[idx] = __float2half_rn(*p);
}

__global__ void convertWo_kernel(const float* __restrict__ Wo) {
    int idx = blockIdx.x * blockDim.x + threadIdx.x;   // over H_SZ*H_SZ
    gWo_hi[idx] = __float2half_rn(Wo[idx]);
}

// ---------------------------------------------------------------------------
// cp.async / ldmatrix helpers
// ---------------------------------------------------------------------------
__device__ __forceinline__ void cp16s(uint32_t sa, const void* g) {
    asm volatile("cp.async.cg.shared.global [%0], [%1], 16;\n" :: "r"(sa), "l"(g));
}

__device__ __forceinline__ void ldsm_x4(uint32_t& r0, uint32_t& r1, uint32_t& r2, uint32_t& r3,
                                        uint32_t addr) {
    asm volatile("ldmatrix.sync.aligned.m8n8.x4.shared.b16 {%0,%1,%2,%3}, [%4];"
                 : "=r"(r0), "=r"(r1), "=r"(r2), "=r"(r3) : "r"(addr));
}

// ---------------------------------------------------------------------------
// fp16-split GEMM: C = A_hi*W + A_lo*W   (two K passes, W fp16-rounded once)
// CTA 128x128, 8 warps of 64x32 (R11-proven). XOR-swizzled 128B smem rows:
//   smem_off(row, cb) = row*128 + (cb ^ ((row&7)*16))
// 3-stage circular cp.async pipeline, one __syncthreads per stage:
//   iter kt: wait_group 1; barrier; load kt+2 into buffer (kt+2)%3 == (kt-1)%3.
// MODE 0: gates GEMM + fused LSTM-cell epilogue. MODE 1: output GEMM + bias.
// ---------------------------------------------------------------------------
template<int KP, int MODE>
__global__ __launch_bounds__(256, 2)
void gemm_kernel(const float* __restrict__ cellv,
                 const float* __restrict__ bF, const float* __restrict__ bI,
                 const float* __restrict__ bO, const float* __restrict__ bG,
                 float* __restrict__ out0, float* __restrict__ out1,
                 const float* __restrict__ bOut) {
    constexpr int NKT = KP / TK;
    constexpr int TOT = 2 * NKT;          // 2 passes (hi, lo) x K

    const __half* __restrict__ Ahi = (MODE == 0) ? gA_hi : gHid_hi;
    const __half* __restrict__ Alo = (MODE == 0) ? gA_lo : gHid_lo;
    const __half* __restrict__ Whi = (MODE == 0) ? gW_hi : gWo_hi;

    extern __shared__ __half smem[];
    const uint32_t smem_u32 = (uint32_t)__cvta_generic_to_shared(smem);
    const uint32_t sA0 = smem_u32;                       // NSTG bufs of TM*128 B
    const uint32_t sB0 = smem_u32 + NSTG * TM * ROWB;    // NSTG bufs of TN*128 B

    const int tid = threadIdx.x;
    const int lane = tid & 31, warp = tid >> 5;
    const int wm = warp >> 2, wn = warp & 3;     // warp grid 2(M) x 4(N), 64x32 each
    const int r = lane >> 2, q = lane & 3;
    const int bm = blockIdx.y, bn = blockIdx.x;

    float acc[4][4][4];
    #pragma unroll
    for (int i = 0; i < 4; i++)
        #pragma unroll
        for (int j = 0; j < 4; j++)
            #pragma unroll
            for (int k = 0; k < 4; k++) acc[i][j][k] = 0.f;

    // cp.async indexing: 8 chunks of 16B per 128B row, 256 threads.
    const int ld_row = tid >> 3;          // 0..31 (+32*t)
    const int ld_cb  = (tid & 7) * 16;    // byte col within row

    // ldmatrix per-thread source rows (within tile) and column bytes.
    const int a_row  = wm * 64 + (lane & 15);                         // + mf*16
    const int a_cb0  = (lane >> 4) * 16;                              // k-half (bytes)
    const int a_xor  = (a_row & 7) * 16;
    const int b_row  = wn * 32 + (lane & 7) + ((lane >> 4) & 1) * 8;  // + nfp*16
    const int b_cb0  = ((lane >> 3) & 1) * 16;
    const int b_xor  = (b_row & 7) * 16;

    auto load_stage = [&](int kt, int buf) {
        int seg = (kt >= NKT) ? 1 : 0;
        int kk = (kt - seg * NKT) * TK;
        const __half* Ap = (seg ? Alo : Ahi) + (size_t)(bm * TM) * KP + kk;
        const __half* Wp = Whi + (size_t)(bn * TN) * KP + kk;
        const uint32_t dA = sA0 + buf * (TM * ROWB);
        const uint32_t dB = sB0 + buf * (TN * ROWB);
        const uint32_t swcb = ld_cb ^ ((ld_row & 7) * 16);   // row&7 invariant under +32
        #pragma unroll
        for (int t = 0; t < 4; t++) {                        // A: 128 rows
            int row = ld_row + t * 32;
            cp16s(dA + row * ROWB + swcb, Ap + (size_t)row * KP + ld_cb / 2);
        }
        #pragma unroll
        for (int t = 0; t < 4; t++) {                        // B: 128 rows
            int row = ld_row + t * 32;
            cp16s(dB + row * ROWB + swcb, Wp + (size_t)row * KP + ld_cb / 2);
        }
        asm volatile("cp.async.commit_group;\n");
    };

    // Prologue: stages 0 and 1 in flight.
    load_stage(0, 0);
    load_stage(1, 1);

    for (int kt = 0; kt < TOT; kt++) {
        const int buf = kt % NSTG;
        asm volatile("cp.async.wait_group 1;\n");   // stage kt resident
        __syncthreads();                            // visibility + WAR fence

        if (kt + 2 < TOT) {
            load_stage(kt + 2, (kt + 2) % NSTG);
        } else {
            asm volatile("cp.async.commit_group;\n");   // keep group counts aligned
        }

        const uint32_t aBuf = sA0 + (uint32_t)(buf * (TM * ROWB));
        const uint32_t bBuf = sB0 + (uint32_t)(buf * (TN * ROWB));

        #pragma unroll
        for (int ks = 0; ks < TK; ks += 16) {
            uint32_t af[4][4], bfr[4][2];
            const uint32_t acol = (uint32_t)((a_cb0 + ks * 2) ^ a_xor);
            const uint32_t bcol = (uint32_t)((b_cb0 + ks * 2) ^ b_xor);
            #pragma unroll
            for (int mf = 0; mf < 4; mf++) {
                uint32_t addr = aBuf + (uint32_t)((a_row + mf * 16) * ROWB) + acol;
                ldsm_x4(af[mf][0], af[mf][1], af[mf][2], af[mf][3], addr);
            }
            #pragma unroll
            for (int nfp = 0; nfp < 2; nfp++) {
                uint32_t addr = bBuf + (uint32_t)((b_row + nfp * 16) * ROWB) + bcol;
                ldsm_x4(bfr[2 * nfp][0], bfr[2 * nfp][1],
                        bfr[2 * nfp + 1][0], bfr[2 * nfp + 1][1], addr);
            }
            #pragma unroll
            for (int mf = 0; mf < 4; mf++)
                #pragma unroll
                for (int nf = 0; nf < 4; nf++) {
                    asm volatile(
                        "mma.sync.aligned.m16n8k16.row.col.f32.f16.f16.f32 "
                        "{%0,%1,%2,%3}, {%4,%5,%6,%7}, {%8,%9}, {%0,%1,%2,%3};\n"
                        : "+f"(acc[mf][nf][0]), "+f"(acc[mf][nf][1]),
                          "+f"(acc[mf][nf][2]), "+f"(acc[mf][nf][3])
                        : "r"(af[mf][0]), "r"(af[mf][1]), "r"(af[mf][2]), "r"(af[mf][3]),
                          "r"(bfr[nf][0]), "r"(bfr[nf][1]));
                }
        }
        // No trailing barrier: next iteration's barrier provides the WAR fence.
    }

    if constexpr (MODE == 0) {
        // Packed column 4h+g. Even lane holds (f,i) pre-acts, odd lane (o,g) of same h.
        const bool writer = ((lane & 1) == 0);
        #pragma unroll
        for (int mf = 0; mf < 4; mf++) {
            #pragma unroll
            for (int nf = 0; nf < 4; nf++) {
                float v0 = acc[mf][nf][0], v1 = acc[mf][nf][1];
                float v2 = acc[mf][nf][2], v3 = acc[mf][nf][3];
                float p0 = __shfl_xor_sync(0xffffffffu, v0, 1);
                float p1 = __shfl_xor_sync(0xffffffffu, v1, 1);
                float p2 = __shfl_xor_sync(0xffffffffu, v2, 1);
                float p3 = __shfl_xor_sync(0xffffffffu, v3, 1);
                if (writer) {
                    int ncol = bn * TN + wn * 32 + nf * 8 + q * 2;   // multiple of 4
                    int h = ncol >> 2;
                    float bf_ = bF[h], bi_ = bI[h], bo_ = bO[h], bg_ = bG[h];
                    int row = bm * TM + wm * 64 + mf * 16 + r;
                    #pragma unroll
                    for (int half = 0; half < 2; half++) {
                        float pf, pi, po, pg;
                        if (half == 0) { pf = v0 + bf_; pi = v1 + bi_; po = p0 + bo_; pg = p1 + bg_; }
                        else           { pf = v2 + bf_; pi = v3 + bi_; po = p2 + bo_; pg = p3 + bg_; }
                        int rr = row + half * 8;
                        float fg = 1.f / (1.f + __expf(-pf));
                        float ig = 1.f / (1.f + __expf(-pi));
                        float og = 1.f / (1.f + __expf(-po));
                        float gg = tanhf(pg);
                        float cold = cellv[rr * H_SZ + h];
                        float ncell = fg * cold + ig * gg;
                        float nhid = og * tanhf(ncell);
                        out0[rr * H_SZ + h] = nhid;    // new_hidden
                        out1[rr * H_SZ + h] = ncell;   // new_cell
                        split_f16(nhid, &gHid_hi[rr * H_SZ + h], &gHid_lo[rr * H_SZ + h]);
                    }
                }
            }
        }
    } else {
        #pragma unroll
        for (int mf = 0; mf < 4; mf++) {
            int row = bm * TM + wm * 64 + mf * 16 + r;
            #pragma unroll
            for (int nf = 0; nf < 4; nf++) {
                int c0 = bn * TN + wn * 32 + nf * 8 + q * 2;
                float b0 = bOut[c0], b1 = bOut[c0 + 1];
                out0[row * H_SZ + c0]           = acc[mf][nf][0] + b0;
                out0[row * H_SZ + c0 + 1]       = acc[mf][nf][1] + b1;
                out0[(row + 8) * H_SZ + c0]     = acc[mf][nf][2] + b0;
                out0[(row + 8) * H_SZ + c0 + 1] = acc[mf][nf][3] + b1;
            }
        }
    }
}

// ---------------------------------------------------------------------------
// Launch
// ---------------------------------------------------------------------------
extern "C" void kernel_launch(void* const* d_in, const int* in_sizes, int n_in,
                              void* d_out, int out_size) {
    const float* X   = (const float*)d_in[0];
    const float* Hv  = (const float*)d_in[1];
    const float* Cv  = (const float*)d_in[2];
    const float* Wxf = (const float*)d_in[3];
    const float* bxf = (const float*)d_in[4];
    const float* Whf = (const float*)d_in[5];
    const float* Wxi = (const float*)d_in[6];
    const float* bxi = (const float*)d_in[7];
    const float* Whi = (const float*)d_in[8];
    const float* Wxo = (const float*)d_in[9];
    const float* bxo = (const float*)d_in[10];
    const float* Who = (const float*)d_in[11];
    const float* Wxg = (const float*)d_in[12];
    const float* bxg = (const float*)d_in[13];
    const float* Whg = (const float*)d_in[14];
    const float* Wo  = (const float*)d_in[15];
    const float* bo  = (const float*)d_in[16];

    float* nh = (float*)d_out;
    float* nc = nh + (size_t)B_SZ * H_SZ;
    float* ov = nc + (size_t)B_SZ * H_SZ;

    convertA_kernel<<<(B_SZ * K1_SZ) / 256, 256>>>(X, Hv);
    convertW_kernel<<<(4 * H_SZ * K1_SZ) / 256, 256>>>(Wxf, Wxi, Wxo, Wxg, Whf, Whi, Who, Whg);
    convertWo_kernel<<<(H_SZ * H_SZ) / 256, 256>>>(Wo);

    cudaFuncSetAttribute(gemm_kernel<K1_SZ, 0>,
                         cudaFuncAttributeMaxDynamicSharedMemorySize, SMEM_BYTES);
    cudaFuncSetAttribute(gemm_kernel<H_SZ, 1>,
                         cudaFuncAttributeMaxDynamicSharedMemorySize, SMEM_BYTES);

    dim3 g1(4 * H_SZ / TN, B_SZ / TM);   // (32, 32) = 1024 CTAs
    gemm_kernel<K1_SZ, 0><<<g1, 256, SMEM_BYTES>>>(Cv, bxf, bxi, bxo, bxg, nh, nc, nullptr);

    dim3 g2(H_SZ / TN, B_SZ / TM);       // (8, 32) = 256 CTAs
    gemm_kernel<H_SZ, 1><<<g2, 256, SMEM_BYTES>>>(nullptr, nullptr, nullptr, nullptr, nullptr,
                                                  ov, nullptr, bo);
}

// round 17
// speedup vs baseline: 2.8298x; 1.6435x over previous
#include <cuda_runtime.h>
#include <cuda_fp16.h>
#include <cstdint>

// Problem sizes (fixed by the reference).
#define B_SZ   4096
#define H_SZ   1024
#define K1_SZ  2048           // IN + H concatenated K for the gates GEMM

// GEMM tiling (R11-proven config): CTA 128x128, 8 warps of 64x32, TK=64, 3 stages.
#define TM 128
#define TN 128
#define TK 64                 // K elems per stage (4 x k16)
#define ROWB 128              // bytes per smem row (TK*2, XOR swizzle, no pad)
#define NSTG 3
#define SMEM_BYTES (NSTG * (TM + TN) * ROWB)   // 98304 (96 KB) -> 2 CTA/SM

// ---------------------------------------------------------------------------
// Scratch: device globals (no allocation allowed anywhere).
// Single-pass fp16: A, W, Hid all fp16-rounded once. C = fl16(A) * fl16(W).
// Error budget (calibrated vs R15 measurement 2.26e-4): ~3e-4 < 1e-3 gate.
// ---------------------------------------------------------------------------
__device__ __half gA[B_SZ * K1_SZ];           // [X | Hprev]
__device__ __half gW[4 * H_SZ * K1_SZ];       // gate-interleaved [Wx|Wh], row = 4h+g
__device__ __half gWo[H_SZ * H_SZ];           // W_out
__device__ __half gHid[B_SZ * H_SZ];          // new_hidden (fp16, for GEMM2)

// ---------------------------------------------------------------------------
// Conversion kernels
// ---------------------------------------------------------------------------
__global__ void convertA_kernel(const float* __restrict__ X, const float* __restrict__ Hv) {
    int idx = blockIdx.x * blockDim.x + threadIdx.x;   // over B_SZ * K1_SZ
    int k = idx & (K1_SZ - 1);
    int m = idx >> 11;
    float v = (k < 1024) ? X[(m << 10) + k] : Hv[(m << 10) + (k - 1024)];
    gA[idx] = __float2half_rn(v);
}

// Packed weight row r = 4*h + gate; cols k<1024 from Wx_gate[h], k>=1024 from Wh_gate[h].
__global__ void convertW_kernel(const float* __restrict__ Wxf, const float* __restrict__ Wxi,
                                const float* __restrict__ Wxo, const float* __restrict__ Wxg,
                                const float* __restrict__ Whf, const float* __restrict__ Whi,
                                const float* __restrict__ Who, const float* __restrict__ Whg) {
    int idx = blockIdx.x * blockDim.x + threadIdx.x;   // over 4*H_SZ * K1_SZ
    int k = idx & (K1_SZ - 1);
    int rrow = idx >> 11;
    int h = rrow >> 2, g = rrow & 3;
    const float* p;
    if (k < 1024) {
        p = (g == 0) ? Wxf : (g == 1) ? Wxi : (g == 2) ? Wxo : Wxg;
        p += (h << 10) + k;
    } else {
        p = (g == 0) ? Whf : (g == 1) ? Whi : (g == 2) ? Who : Whg;
        p += (h << 10) + (k - 1024);
    }
    gW[idx] = __float2half_rn(*p);
}

__global__ void convertWo_kernel(const float* __restrict__ Wo) {
    int idx = blockIdx.x * blockDim.x + threadIdx.x;   // over H_SZ*H_SZ
    gWo[idx] = __float2half_rn(Wo[idx]);
}

// ---------------------------------------------------------------------------
// cp.async / ldmatrix helpers
// ---------------------------------------------------------------------------
__device__ __forceinline__ void cp16s(uint32_t sa, const void* g) {
    asm volatile("cp.async.cg.shared.global [%0], [%1], 16;\n" :: "r"(sa), "l"(g));
}

__device__ __forceinline__ void ldsm_x4(uint32_t& r0, uint32_t& r1, uint32_t& r2, uint32_t& r3,
                                        uint32_t addr) {
    asm volatile("ldmatrix.sync.aligned.m8n8.x4.shared.b16 {%0,%1,%2,%3}, [%4];"
                 : "=r"(r0), "=r"(r1), "=r"(r2), "=r"(r3) : "r"(addr));
}

// ---------------------------------------------------------------------------
// Single-pass fp16 GEMM: C = fl16(A) * fl16(W)
// CTA 128x128, 8 warps of 64x32 (R11-proven). XOR-swizzled 128B smem rows:
//   smem_off(row, cb) = row*128 + (cb ^ ((row&7)*16))
// 3-stage circular cp.async pipeline, one __syncthreads per stage:
//   iter kt: wait_group 1; barrier; load kt+2 into buffer (kt+2)%3 == (kt-1)%3.
// MODE 0: gates GEMM + fused LSTM-cell epilogue. MODE 1: output GEMM + bias.
// ---------------------------------------------------------------------------
template<int KP, int MODE>
__global__ __launch_bounds__(256, 2)
void gemm_kernel(const float* __restrict__ cellv,
                 const float* __restrict__ bF, const float* __restrict__ bI,
                 const float* __restrict__ bO, const float* __restrict__ bG,
                 float* __restrict__ out0, float* __restrict__ out1,
                 const float* __restrict__ bOut) {
    constexpr int TOT = KP / TK;          // single pass over K

    const __half* __restrict__ Ain = (MODE == 0) ? gA : gHid;
    const __half* __restrict__ Win = (MODE == 0) ? gW : gWo;

    extern __shared__ __half smem[];
    const uint32_t smem_u32 = (uint32_t)__cvta_generic_to_shared(smem);
    const uint32_t sA0 = smem_u32;                       // NSTG bufs of TM*128 B
    const uint32_t sB0 = smem_u32 + NSTG * TM * ROWB;    // NSTG bufs of TN*128 B

    const int tid = threadIdx.x;
    const int lane = tid & 31, warp = tid >> 5;
    const int wm = warp >> 2, wn = warp & 3;     // warp grid 2(M) x 4(N), 64x32 each
    const int r = lane >> 2, q = lane & 3;
    const int bm = blockIdx.y, bn = blockIdx.x;

    float acc[4][4][4];
    #pragma unroll
    for (int i = 0; i < 4; i++)
        #pragma unroll
        for (int j = 0; j < 4; j++)
            #pragma unroll
            for (int k = 0; k < 4; k++) acc[i][j][k] = 0.f;

    // cp.async indexing: 8 chunks of 16B per 128B row, 256 threads.
    const int ld_row = tid >> 3;          // 0..31 (+32*t)
    const int ld_cb  = (tid & 7) * 16;    // byte col within row

    // ldmatrix per-thread source rows (within tile) and column bytes.
    const int a_row  = wm * 64 + (lane & 15);                         // + mf*16
    const int a_cb0  = (lane >> 4) * 16;                              // k-half (bytes)
    const int a_xor  = (a_row & 7) * 16;
    const int b_row  = wn * 32 + (lane & 7) + ((lane >> 4) & 1) * 8;  // + nfp*16
    const int b_cb0  = ((lane >> 3) & 1) * 16;
    const int b_xor  = (b_row & 7) * 16;

    auto load_stage = [&](int kt, int buf) {
        int kk = kt * TK;
        const __half* Ap = Ain + (size_t)(bm * TM) * KP + kk;
        const __half* Wp = Win + (size_t)(bn * TN) * KP + kk;
        const uint32_t dA = sA0 + buf * (TM * ROWB);
        const uint32_t dB = sB0 + buf * (TN * ROWB);
        const uint32_t swcb = ld_cb ^ ((ld_row & 7) * 16);   // row&7 invariant under +32
        #pragma unroll
        for (int t = 0; t < 4; t++) {                        // A: 128 rows
            int row = ld_row + t * 32;
            cp16s(dA + row * ROWB + swcb, Ap + (size_t)row * KP + ld_cb / 2);
        }
        #pragma unroll
        for (int t = 0; t < 4; t++) {                        // B: 128 rows
            int row = ld_row + t * 32;
            cp16s(dB + row * ROWB + swcb, Wp + (size_t)row * KP + ld_cb / 2);
        }
        asm volatile("cp.async.commit_group;\n");
    };

    // Prologue: stages 0 and 1 in flight.
    load_stage(0, 0);
    load_stage(1, 1);

    for (int kt = 0; kt < TOT; kt++) {
        const int buf = kt % NSTG;
        asm volatile("cp.async.wait_group 1;\n");   // stage kt resident
        __syncthreads();                            // visibility + WAR fence

        if (kt + 2 < TOT) {
            load_stage(kt + 2, (kt + 2) % NSTG);
        } else {
            asm volatile("cp.async.commit_group;\n");   // keep group counts aligned
        }

        const uint32_t aBuf = sA0 + (uint32_t)(buf * (TM * ROWB));
        const uint32_t bBuf = sB0 + (uint32_t)(buf * (TN * ROWB));

        #pragma unroll
        for (int ks = 0; ks < TK; ks += 16) {
            uint32_t af[4][4], bfr[4][2];
            const uint32_t acol = (uint32_t)((a_cb0 + ks * 2) ^ a_xor);
            const uint32_t bcol = (uint32_t)((b_cb0 + ks * 2) ^ b_xor);
            #pragma unroll
            for (int mf = 0; mf < 4; mf++) {
                uint32_t addr = aBuf + (uint32_t)((a_row + mf * 16) * ROWB) + acol;
                ldsm_x4(af[mf][0], af[mf][1], af[mf][2], af[mf][3], addr);
            }
            #pragma unroll
            for (int nfp = 0; nfp < 2; nfp++) {
                uint32_t addr = bBuf + (uint32_t)((b_row + nfp * 16) * ROWB) + bcol;
                ldsm_x4(bfr[2 * nfp][0], bfr[2 * nfp][1],
                        bfr[2 * nfp + 1][0], bfr[2 * nfp + 1][1], addr);
            }
            #pragma unroll
            for (int mf = 0; mf < 4; mf++)
                #pragma unroll
                for (int nf = 0; nf < 4; nf++) {
                    asm volatile(
                        "mma.sync.aligned.m16n8k16.row.col.f32.f16.f16.f32 "
                        "{%0,%1,%2,%3}, {%4,%5,%6,%7}, {%8,%9}, {%0,%1,%2,%3};\n"
                        : "+f"(acc[mf][nf][0]), "+f"(acc[mf][nf][1]),
                          "+f"(acc[mf][nf][2]), "+f"(acc[mf][nf][3])
                        : "r"(af[mf][0]), "r"(af[mf][1]), "r"(af[mf][2]), "r"(af[mf][3]),
                          "r"(bfr[nf][0]), "r"(bfr[nf][1]));
                }
        }
        // No trailing barrier: next iteration's barrier provides the WAR fence.
    }

    if constexpr (MODE == 0) {
        // Packed column 4h+g. Even lane holds (f,i) pre-acts, odd lane (o,g) of same h.
        const bool writer = ((lane & 1) == 0);
        #pragma unroll
        for (int mf = 0; mf < 4; mf++) {
            #pragma unroll
            for (int nf = 0; nf < 4; nf++) {
                float v0 = acc[mf][nf][0], v1 = acc[mf][nf][1];
                float v2 = acc[mf][nf][2], v3 = acc[mf][nf][3];
                float p0 = __shfl_xor_sync(0xffffffffu, v0, 1);
                float p1 = __shfl_xor_sync(0xffffffffu, v1, 1);
                float p2 = __shfl_xor_sync(0xffffffffu, v2, 1);
                float p3 = __shfl_xor_sync(0xffffffffu, v3, 1);
                if (writer) {
                    int ncol = bn * TN + wn * 32 + nf * 8 + q * 2;   // multiple of 4
                    int h = ncol >> 2;
                    float bf_ = bF[h], bi_ = bI[h], bo_ = bO[h], bg_ = bG[h];
                    int row = bm * TM + wm * 64 + mf * 16 + r;
                    #pragma unroll
                    for (int half = 0; half < 2; half++) {
                        float pf, pi, po, pg;
                        if (half == 0) { pf = v0 + bf_; pi = v1 + bi_; po = p0 + bo_; pg = p1 + bg_; }
                        else           { pf = v2 + bf_; pi = v3 + bi_; po = p2 + bo_; pg = p3 + bg_; }
                        int rr = row + half * 8;
                        float fg = 1.f / (1.f + __expf(-pf));
                        float ig = 1.f / (1.f + __expf(-pi));
                        float og = 1.f / (1.f + __expf(-po));
                        float gg = tanhf(pg);
                        float cold = cellv[rr * H_SZ + h];
                        float ncell = fg * cold + ig * gg;
                        float nhid = og * tanhf(ncell);
                        out0[rr * H_SZ + h] = nhid;    // new_hidden
                        out1[rr * H_SZ + h] = ncell;   // new_cell
                        gHid[rr * H_SZ + h] = __float2half_rn(nhid);
                    }
                }
            }
        }
    } else {
        #pragma unroll
        for (int mf = 0; mf < 4; mf++) {
            int row = bm * TM + wm * 64 + mf * 16 + r;
            #pragma unroll
            for (int nf = 0; nf < 4; nf++) {
                int c0 = bn * TN + wn * 32 + nf * 8 + q * 2;
                float b0 = bOut[c0], b1 = bOut[c0 + 1];
                out0[row * H_SZ + c0]           = acc[mf][nf][0] + b0;
                out0[row * H_SZ + c0 + 1]       = acc[mf][nf][1] + b1;
                out0[(row + 8) * H_SZ + c0]     = acc[mf][nf][2] + b0;
                out0[(row + 8) * H_SZ + c0 + 1] = acc[mf][nf][3] + b1;
            }
        }
    }
}

// ---------------------------------------------------------------------------
// Launch
// ---------------------------------------------------------------------------
extern "C" void kernel_launch(void* const* d_in, const int* in_sizes, int n_in,
                              void* d_out, int out_size) {
    const float* X   = (const float*)d_in[0];
    const float* Hv  = (const float*)d_in[1];
    const float* Cv  = (const float*)d_in[2];
    const float* Wxf = (const float*)d_in[3];
    const float* bxf = (const float*)d_in[4];
    const float* Whf = (const float*)d_in[5];
    const float* Wxi = (const float*)d_in[6];
    const float* bxi = (const float*)d_in[7];
    const float* Whi = (const float*)d_in[8];
    const float* Wxo = (const float*)d_in[9];
    const float* bxo = (const float*)d_in[10];
    const float* Who = (const float*)d_in[11];
    const float* Wxg = (const float*)d_in[12];
    const float* bxg = (const float*)d_in[13];
    const float* Whg = (const float*)d_in[14];
    const float* Wo  = (const float*)d_in[15];
    const float* bo  = (const float*)d_in[16];

    float* nh = (float*)d_out;
    float* nc = nh + (size_t)B_SZ * H_SZ;
    float* ov = nc + (size_t)B_SZ * H_SZ;

    convertA_kernel<<<(B_SZ * K1_SZ) / 256, 256>>>(X, Hv);
    convertW_kernel<<<(4 * H_SZ * K1_SZ) / 256, 256>>>(Wxf, Wxi, Wxo, Wxg, Whf, Whi, Who, Whg);
    convertWo_kernel<<<(H_SZ * H_SZ) / 256, 256>>>(Wo);

    cudaFuncSetAttribute(gemm_kernel<K1_SZ, 0>,
                         cudaFuncAttributeMaxDynamicSharedMemorySize, SMEM_BYTES);
    cudaFuncSetAttribute(gemm_kernel<H_SZ, 1>,
                         cudaFuncAttributeMaxDynamicSharedMemorySize, SMEM_BYTES);

    dim3 g1(4 * H_SZ / TN, B_SZ / TM);   // (32, 32) = 1024 CTAs
    gemm_kernel<K1_SZ, 0><<<g1, 256, SMEM_BYTES>>>(Cv, bxf, bxi, bxo, bxg, nh, nc, nullptr);

    dim3 g2(H_SZ / TN, B_SZ / TM);       // (8, 32) = 256 CTAs
    gemm_kernel<H_SZ, 1><<<g2, 256, SMEM_BYTES>>>(nullptr, nullptr, nullptr, nullptr, nullptr,
                                                  ov, nullptr, bo);
}